// round 17
// baseline (speedup 1.0000x reference)
#include <cuda_runtime.h>
#include <cuda_fp16.h>
#include <cstdint>

#define BB 8
#define SS 1024
#define DD 512
#define HH 8

#define STG_H (128*64*2)     // halves per stage (A 128x64 + B 128x64)

// ---------------- fp16 staged tensors ----------------
__device__ __align__(256) __half g_xh [BB*SS*DD];           // X [B,S,D]
__device__ __align__(256) __half g_xt [BB*DD*SS];           // X^T [B,D,S]
__device__ __align__(256) __half g_woh[DD*HH*DD];           // Wo fp16
__device__ __align__(256) __half g_wqt[HH*DD*DD];
__device__ __align__(256) __half g_wkt[HH*DD*DD];
__device__ __align__(256) __half g_wvt[HH*DD*DD];
__device__ __align__(256) __half g_nh [HH*DD*DD];           // N per head [i][j]
__device__ __align__(256) __half g_gcat[DD*HH*DD];          // Ghat [o][4096]
__device__ __align__(256) __half g_g1 [BB*DD*DD];           // G1_b = X^T X
__device__ __align__(256) __half g_ft [(size_t)BB*DD*HH*DD];// FTT_b[i][h*512+j]
__device__ __align__(256) __half g_m2 [BB*DD*DD];           // M2_b[o][i]
// split-K partials (fp32)
__device__ __align__(256) float g_m2p[(size_t)BB*4*DD*DD];  // 33.5 MB
__device__ __align__(256) float g_g1p[(size_t)BB*2*DD*DD];  // 16.8 MB
__device__ float g_cspart[BB*8*DD];
// fp32 small
__device__ float g_r[HH*DD], g_chat[DD];
__device__ float g_vbar[BB*HH];
__device__ float g_cs[BB*DD];
__device__ float g_w2[BB*HH*DD];
__device__ float g_rm[BB*HH*SS];
__device__ float g_vx[BB*HH*DD];
__device__ float g_w1[BB*HH*DD];
__device__ float g_a [BB*HH*DD];
__device__ float g_c2[BB*HH*DD];
__device__ float g_cb[BB*DD];

// ---------------- helpers ----------------
__device__ __forceinline__ unsigned smem_u32(const void* p) {
    return (unsigned)__cvta_generic_to_shared(p);
}
__device__ __forceinline__ void cp16(void* dst, const void* src) {
    asm volatile("cp.async.cg.shared.global [%0], [%1], 16;\n"
                 :: "r"(smem_u32(dst)), "l"(src));
}

// ---------------- fp16 GEMM mainloop (validated, unchanged) ----------------
template<int KT>
__device__ __forceinline__ void gemm_h(const __half* __restrict__ Ag,
                                       const __half* __restrict__ Bg,
                                       int lda, int ldb,
                                       __half* sm, float (&acc)[4][8][4])
{
    const int tid  = threadIdx.x;
    const int lane = tid & 31;
    const int warp = tid >> 5;
    const int wm = (warp & 1) * 64;
    const int wn = (warp >> 1) * 64;

#pragma unroll
    for (int mi = 0; mi < 4; mi++)
#pragma unroll
        for (int ni = 0; ni < 8; ni++)
#pragma unroll
            for (int r = 0; r < 4; r++) acc[mi][ni][r] = 0.f;

    const int srow = tid >> 3;
    const int sch  = tid & 7;

    auto stage = [&](int s, int kt) {
        __half* sA = sm + s * STG_H;
        __half* sB = sA + 128 * 64;
        const __half* ap = Ag + (size_t)srow * lda + kt * 64 + sch * 8;
        const __half* bp = Bg + (size_t)srow * ldb + kt * 64 + sch * 8;
#pragma unroll
        for (int i = 0; i < 8; i++) {
            int r = srow + i * 16;
            int sw = (sch ^ (r & 7)) * 8;
            cp16(sA + r * 64 + sw, ap + (size_t)(i * 16) * lda);
            cp16(sB + r * 64 + sw, bp + (size_t)(i * 16) * ldb);
        }
        asm volatile("cp.async.commit_group;\n");
    };

    stage(0, 0);
    stage(1, 1);

#pragma unroll 1
    for (int kt = 0; kt < KT; kt++) {
        if (kt < KT - 1) asm volatile("cp.async.wait_group 1;\n");
        else             asm volatile("cp.async.wait_group 0;\n");
        __syncthreads();

        if (kt + 2 < KT) stage((kt + 2) % 3, kt + 2);

        const __half* sA = sm + (kt % 3) * STG_H;
        const __half* sB = sA + 128 * 64;

#pragma unroll
        for (int ks = 0; ks < 4; ks++) {
            uint32_t a[4][4];
#pragma unroll
            for (int mi = 0; mi < 4; mi++) {
                int r  = wm + mi * 16 + (lane & 15);
                int ch = 2 * ks + (lane >> 4);
                unsigned ad = smem_u32(sA + r * 64 + ((ch ^ (r & 7)) * 8));
                asm volatile("ldmatrix.sync.aligned.m8n8.x4.shared.b16 {%0,%1,%2,%3}, [%4];"
                             : "=r"(a[mi][0]), "=r"(a[mi][1]), "=r"(a[mi][2]), "=r"(a[mi][3])
                             : "r"(ad));
            }
            uint32_t b[8][2];
#pragma unroll
            for (int nj = 0; nj < 4; nj++) {
                int nr = wn + nj * 16 + ((lane >> 4) << 3) + (lane & 7);
                int ch = 2 * ks + ((lane >> 3) & 1);
                unsigned ad = smem_u32(sB + nr * 64 + ((ch ^ (nr & 7)) * 8));
                uint32_t r0, r1, r2, r3;
                asm volatile("ldmatrix.sync.aligned.m8n8.x4.shared.b16 {%0,%1,%2,%3}, [%4];"
                             : "=r"(r0), "=r"(r1), "=r"(r2), "=r"(r3) : "r"(ad));
                b[nj*2][0] = r0;  b[nj*2][1] = r1;
                b[nj*2+1][0] = r2; b[nj*2+1][1] = r3;
            }
#pragma unroll
            for (int mi = 0; mi < 4; mi++)
#pragma unroll
                for (int ni = 0; ni < 8; ni++) {
                    asm volatile(
                        "mma.sync.aligned.m16n8k16.row.col.f32.f16.f16.f32 "
                        "{%0,%1,%2,%3}, {%4,%5,%6,%7}, {%8,%9}, {%0,%1,%2,%3};"
                        : "+f"(acc[mi][ni][0]), "+f"(acc[mi][ni][1]),
                          "+f"(acc[mi][ni][2]), "+f"(acc[mi][ni][3])
                        : "r"(a[mi][0]), "r"(a[mi][1]), "r"(a[mi][2]), "r"(a[mi][3]),
                          "r"(b[ni][0]), "r"(b[ni][1]));
                }
        }
    }
}

#define EPI_ROW(wm, mi, r)  ((wm) + (mi)*16 + (lane >> 2) + (((r) >> 1) << 3))
#define EPI_COL(wn, ni, r)  ((wn) + (ni)*8 + ((lane & 3) << 1) + ((r) & 1))

// ---------------- fp16 conversion (X and Wo only) ----------------
__global__ void k_cvt(const float* __restrict__ X, const float* __restrict__ Wo)
{
    const int stride = gridDim.x * blockDim.x;
    const int i0 = blockIdx.x * blockDim.x + threadIdx.x;
    for (int i = i0; i < BB*SS*DD; i += stride) g_xh[i]  = __float2half_rn(X[i]);
    for (int i = i0; i < DD*HH*DD; i += stride) g_woh[i] = __float2half_rn(Wo[i]);
}

// ---------------- weight transposes: fp32 -> fp16 transposed ----------------
__global__ void k_trw(const float* __restrict__ Wq, const float* __restrict__ Wk,
                      const float* __restrict__ Wv)
{
    const int m = blockIdx.z;
    const float* src;  __half* dst;
    if (m < 8)       { src = Wq + (size_t)m * DD * DD;      dst = g_wqt + (size_t)m * DD * DD; }
    else if (m < 16) { src = Wk + (size_t)(m-8) * DD * DD;  dst = g_wkt + (size_t)(m-8) * DD * DD; }
    else             { src = Wv + (size_t)(m-16) * DD * DD; dst = g_wvt + (size_t)(m-16) * DD * DD; }
    __shared__ __half T[32][33];
    const int r0 = blockIdx.y * 32, c0 = blockIdx.x * 32;
    const int tx = threadIdx.x, ty = threadIdx.y;
#pragma unroll
    for (int k = 0; k < 4; k++)
        T[ty + 8*k][tx] = __float2half_rn(src[(size_t)(r0 + ty + 8*k) * DD + c0 + tx]);
    __syncthreads();
#pragma unroll
    for (int k = 0; k < 4; k++) dst[(size_t)(c0 + ty + 8*k) * DD + r0 + tx] = T[tx][ty + 8*k];
}

__global__ void k_trx()
{
    const int b = blockIdx.z;
    const __half* src = g_xh + (size_t)b * SS * DD;
    __half* dst = g_xt + (size_t)b * DD * SS;
    __shared__ __half T[32][33];
    const int r0 = blockIdx.y * 32, c0 = blockIdx.x * 32;
    const int tx = threadIdx.x, ty = threadIdx.y;
#pragma unroll
    for (int k = 0; k < 4; k++) T[ty + 8*k][tx] = src[(size_t)(r0 + ty + 8*k) * DD + c0 + tx];
    __syncthreads();
#pragma unroll
    for (int k = 0; k < 4; k++) dst[(size_t)(c0 + ty + 8*k) * SS + r0 + tx] = T[tx][ty + 8*k];
}

// ---------------- r_h[i] = wkt_h[i,:].bq_h ----------------
__global__ void k_r(const float* __restrict__ bq)
{
    const int h = blockIdx.x;
    const int warp = threadIdx.x >> 5, lane = threadIdx.x & 31;
    __shared__ float sb[DD];
    for (int i = threadIdx.x; i < DD; i += 256) sb[i] = bq[h * DD + i];
    __syncthreads();
    const int i = blockIdx.y * 8 + warp;
    const __half* row = g_wkt + (size_t)h * DD * DD + (size_t)i * DD;
    float a = 0.f;
#pragma unroll
    for (int k = 0; k < 16; k++) a += __half2float(row[lane + 32 * k]) * sb[lane + 32 * k];
#pragma unroll
    for (int o = 16; o > 0; o >>= 1) a += __shfl_xor_sync(0xffffffffu, a, o);
    if (lane == 0) g_r[h * DD + i] = a;
}

// chat[o] = Wo[o,:].bv + bo[o]
__global__ void k_chat(const float* __restrict__ Wo, const float* __restrict__ bv,
                       const float* __restrict__ bo)
{
    const int o = blockIdx.x, t = threadIdx.x;
    float a = 0.f;
    for (int k = t; k < HH * DD; k += 256) a += Wo[(size_t)o * (HH*DD) + k] * bv[k];
    __shared__ float red[256];
    red[t] = a;
    __syncthreads();
    for (int s = 128; s > 0; s >>= 1) {
        if (t < s) red[t] += red[t + s];
        __syncthreads();
    }
    if (t == 0) g_chat[o] = red[0] + bo[o];
}

// ---------------- colsum: 2-stage parallel ----------------
__global__ void k_colsum1(const float* __restrict__ X)
{
    const int b = blockIdx.x, tc = blockIdx.y;
    const int j = threadIdx.x;                    // 0..511
    const float* x = X + (size_t)b * SS * DD + (size_t)(tc * 128) * DD + j;
    float a = 0.f;
#pragma unroll 8
    for (int t = 0; t < 128; t++) a += x[(size_t)t * DD];
    g_cspart[(b * 8 + tc) * DD + j] = a;
}
__global__ void k_csred()
{
    const int b = blockIdx.x, j = threadIdx.x;
    float a = 0.f;
#pragma unroll
    for (int tc = 0; tc < 8; tc++) a += g_cspart[(b * 8 + tc) * DD + j];
    g_cs[b * DD + j] = a;
}

// vbar[z] = xbar_b . r_h
__global__ void k_vbar()
{
    const int z = blockIdx.x, b = z >> 3, h = z & 7;
    const int lane = threadIdx.x;
    const float invS = 1.0f / SS;
    float a = 0.f;
#pragma unroll
    for (int k = 0; k < 16; k++) {
        int e = lane + 32 * k;
        a += g_cs[b * DD + e] * g_r[h * DD + e];
    }
#pragma unroll
    for (int o = 16; o > 0; o >>= 1) a += __shfl_xor_sync(0xffffffffu, a, o);
    if (lane == 0) g_vbar[z] = a * invS;
}

// w1: weights-outer over 8 batches
__global__ void k_w1(const float* __restrict__ Wv)
{
    const int h = blockIdx.x;
    const int warp = threadIdx.x >> 5, lane = threadIdx.x & 31;
    __shared__ float scs[BB][DD];
    for (int i = threadIdx.x; i < BB * DD; i += 256) scs[i >> 9][i & 511] = g_cs[i];
    __syncthreads();
    const int e = blockIdx.y * 8 + warp;
    const float* wrow = Wv + (size_t)h * DD * DD + (size_t)e * DD;
    float wv[16];
#pragma unroll
    for (int k = 0; k < 16; k++) wv[k] = wrow[lane + 32 * k];
#pragma unroll
    for (int b = 0; b < BB; b++) {
        float a = 0.f;
#pragma unroll
        for (int k = 0; k < 16; k++) a += wv[k] * scs[b][lane + 32 * k];
#pragma unroll
        for (int o = 16; o > 0; o >>= 1) a += __shfl_xor_sync(0xffffffffu, a, o);
        if (lane == 0) g_w1[(b * HH + h) * DD + e] = a;
    }
}

// w2[z][i] = N_h[i,:] . xbar_b
__global__ void k_w2()
{
    const int h = blockIdx.x;
    const int warp = threadIdx.x >> 5, lane = threadIdx.x & 31;
    __shared__ float sx[BB][DD];
    const float invS = 1.0f / SS;
    for (int i = threadIdx.x; i < BB * DD; i += 256) sx[i >> 9][i & 511] = g_cs[i] * invS;
    __syncthreads();
    const int i = blockIdx.y * 8 + warp;
    const __half* nrow = g_nh + (size_t)h * DD * DD + (size_t)i * DD;
    float nv[16];
#pragma unroll
    for (int k = 0; k < 16; k++) nv[k] = __half2float(nrow[lane + 32 * k]);
#pragma unroll
    for (int b = 0; b < BB; b++) {
        float a = 0.f;
#pragma unroll
        for (int k = 0; k < 16; k++) a += nv[k] * sx[b][lane + 32 * k];
#pragma unroll
        for (int o = 16; o > 0; o >>= 1) a += __shfl_xor_sync(0xffffffffu, a, o);
        if (lane == 0) g_w2[(b * HH + h) * DD + i] = a;
    }
}

// vx[z][j] = (G1_b r_h)[j]
__global__ void k_vx()
{
    const int b = blockIdx.x;
    const int warp = threadIdx.x >> 5, lane = threadIdx.x & 31;
    __shared__ float sr[HH][DD];
    for (int i = threadIdx.x; i < HH * DD; i += 256) sr[i >> 9][i & 511] = g_r[i];
    __syncthreads();
    const int j = blockIdx.y * 8 + warp;
    const __half* grow = g_g1 + (size_t)b * DD * DD + (size_t)j * DD;
    float gv[16];
#pragma unroll
    for (int k = 0; k < 16; k++) gv[k] = __half2float(grow[lane + 32 * k]);
#pragma unroll
    for (int h = 0; h < HH; h++) {
        float a = 0.f;
#pragma unroll
        for (int k = 0; k < 16; k++) a += gv[k] * sr[h][lane + 32 * k];
#pragma unroll
        for (int o = 16; o > 0; o >>= 1) a += __shfl_xor_sync(0xffffffffu, a, o);
        if (lane == 0) g_vx[(b * HH + h) * DD + j] = a;
    }
}

// rm[z][s] = (x_s . w2[z] + vbar[z]) / D^2
__global__ void k_rm()
{
    const int warp = threadIdx.x >> 5, lane = threadIdx.x & 31;
    const int tok = blockIdx.x * 4 + warp;
    const int b = tok >> 10, ss = tok & 1023;
    __shared__ float sw[HH * DD];
    for (int i = threadIdx.x; i < HH * DD; i += 128) sw[i] = g_w2[(b * HH) * DD + i];
    __syncthreads();
    const __half* x = g_xh + (size_t)tok * DD;
    float xv[16];
#pragma unroll
    for (int k = 0; k < 16; k++) xv[k] = __half2float(x[lane + 32 * k]);
    const float invD2 = 1.0f / 262144.0f;
#pragma unroll
    for (int h = 0; h < HH; h++) {
        float d = 0.f;
#pragma unroll
        for (int k = 0; k < 16; k++) d += xv[k] * sw[h * DD + lane + 32 * k];
#pragma unroll
        for (int o = 16; o > 0; o >>= 1) d += __shfl_xor_sync(0xffffffffu, d, o);
        if (lane == 0)
            g_rm[(b * HH + h) * SS + ss] = (d + g_vbar[b * HH + h]) * invD2;
    }
}

// ---------------- mgemm: z<8 -> N; z>=8 -> Ghat ----------------
__global__ void __launch_bounds__(128, 2) k_mgemm()
{
    extern __shared__ __half sm[];
    const int m0 = blockIdx.x * 128, n0 = blockIdx.y * 128, z = blockIdx.z;
    float acc[4][8][4];
    const int lane = threadIdx.x & 31, warp = threadIdx.x >> 5;
    const int wm = (warp & 1) * 64, wn = (warp >> 1) * 64;

    if (z < 8) {
        const __half* A = g_wkt + (size_t)z * DD * DD + (size_t)m0 * DD;
        const __half* B = g_wqt + (size_t)z * DD * DD + (size_t)n0 * DD;
        gemm_h<8>(A, B, DD, DD, sm, acc);
        __half* Cn = g_nh + (size_t)z * DD * DD;
#pragma unroll
        for (int mi = 0; mi < 4; mi++)
#pragma unroll
            for (int ni = 0; ni < 8; ni++)
#pragma unroll
                for (int r = 0; r < 4; r++) {
                    int j = m0 + EPI_ROW(wm, mi, r);
                    int i = n0 + EPI_COL(wn, ni, r);
                    Cn[(size_t)i * DD + j] = __float2half_rn(acc[mi][ni][r]);
                }
    } else {
        const int h = z - 8;
        const __half* A = g_woh + (size_t)m0 * (HH*DD) + h * DD;
        const __half* B = g_wvt + (size_t)h * DD * DD + (size_t)n0 * DD;
        gemm_h<8>(A, B, HH*DD, DD, sm, acc);
#pragma unroll
        for (int mi = 0; mi < 4; mi++)
#pragma unroll
            for (int ni = 0; ni < 8; ni++)
#pragma unroll
                for (int r = 0; r < 4; r++)
                    g_gcat[(size_t)(m0 + EPI_ROW(wm, mi, r)) * (HH*DD) + h * DD + n0 + EPI_COL(wn, ni, r)] =
                        __float2half_rn(acc[mi][ni][r]);
    }
}

// ---------------- G1 split-K x2: z = b*2+kc ----------------
__global__ void __launch_bounds__(128, 2) k_G1s()
{
    extern __shared__ __half sm[];
    const int m0 = blockIdx.x * 128, n0 = blockIdx.y * 128, z = blockIdx.z;
    const int b = z >> 1, kc = z & 1;
    float acc[4][8][4];
    gemm_h<8>(g_xt + (size_t)b * DD * SS + (size_t)m0 * SS + kc * 512,
              g_xt + (size_t)b * DD * SS + (size_t)n0 * SS + kc * 512, SS, SS, sm, acc);

    float* C = g_g1p + (size_t)z * DD * DD;
    const int lane = threadIdx.x & 31, warp = threadIdx.x >> 5;
    const int wm = (warp & 1) * 64, wn = (warp >> 1) * 64;
#pragma unroll
    for (int mi = 0; mi < 4; mi++)
#pragma unroll
        for (int ni = 0; ni < 8; ni++)
#pragma unroll
            for (int r = 0; r < 4; r++)
                C[(size_t)(m0 + EPI_ROW(wm, mi, r)) * DD + n0 + EPI_COL(wn, ni, r)] = acc[mi][ni][r];
}
__global__ void k_g1red()
{
    const int b = blockIdx.x, e = blockIdx.y, e2 = threadIdx.x;
    float a = g_g1p[((size_t)(b*2)   * DD + e) * DD + e2]
            + g_g1p[((size_t)(b*2+1) * DD + e) * DD + e2];
    g_g1[((size_t)b * DD + e) * DD + e2] = __float2half_rn(a);
}

// ---------------- FTT_b[i][h*512+j] = sum_e N_h[i,e] G1_b[j,e] ----------------
__global__ void __launch_bounds__(128, 2) k_F()
{
    extern __shared__ __half sm[];
    const int m0 = blockIdx.x * 128, n0 = blockIdx.y * 128, z = blockIdx.z;
    const int b = z >> 3, h = z & 7;
    float acc[4][8][4];
    gemm_h<8>(g_nh + (size_t)h * DD * DD + (size_t)m0 * DD,
              g_g1 + (size_t)b * DD * DD + (size_t)n0 * DD,
              DD, DD, sm, acc);

    __half* C = g_ft + (size_t)b * DD * (HH*DD);
    const int lane = threadIdx.x & 31, warp = threadIdx.x >> 5;
    const int wm = (warp & 1) * 64, wn = (warp >> 1) * 64;
#pragma unroll
    for (int mi = 0; mi < 4; mi++)
#pragma unroll
        for (int ni = 0; ni < 8; ni++)
#pragma unroll
            for (int r = 0; r < 4; r++) {
                int i = m0 + EPI_ROW(wm, mi, r);
                int j = n0 + EPI_COL(wn, ni, r);
                C[(size_t)i * (HH*DD) + h * DD + j] = __float2half_rn(acc[mi][ni][r]);
            }
}

// ---------------- a/c2: weights-outer ----------------
__global__ void k_ac2(const float* __restrict__ Wo)
{
    const int h = blockIdx.x;
    const int warp = threadIdx.x >> 5, lane = threadIdx.x & 31;
    __shared__ float sw1[BB][DD];
    __shared__ float svx[BB][DD];
    for (int i = threadIdx.x; i < BB * DD; i += 256) {
        int b = i >> 9, e = i & 511;
        sw1[b][e] = g_w1[(b * HH + h) * DD + e];
        svx[b][e] = g_vx[(b * HH + h) * DD + e];
    }
    __syncthreads();
    const int o = blockIdx.y * 8 + warp;
    const float*  worow = Wo + (size_t)o * (HH*DD) + h * DD;
    const __half* grow  = g_gcat + (size_t)o * (HH*DD) + h * DD;
    float wv[16], gv[16];
#pragma unroll
    for (int k = 0; k < 16; k++) {
        wv[k] = worow[lane + 32 * k];
        gv[k] = __half2float(grow[lane + 32 * k]);
    }
#pragma unroll
    for (int b = 0; b < BB; b++) {
        float a = 0.f, c = 0.f;
#pragma unroll
        for (int k = 0; k < 16; k++) {
            a += wv[k] * sw1[b][lane + 32 * k];
            c += gv[k] * svx[b][lane + 32 * k];
        }
#pragma unroll
        for (int off = 16; off > 0; off >>= 1) {
            a += __shfl_xor_sync(0xffffffffu, a, off);
            c += __shfl_xor_sync(0xffffffffu, c, off);
        }
        if (lane == 0) {
            g_a [(b * HH + h) * DD + o] = a;
            g_c2[(b * HH + h) * DD + o] = c;
        }
    }
}

// cb_b[o]
__global__ void k_cb()
{
    const int b = blockIdx.x;
    const int o = blockIdx.y * 128 + threadIdx.x;
    float sa = 0.f, sc = 0.f;
#pragma unroll
    for (int h = 0; h < HH; h++) {
        sa += g_a [(b * HH + h) * DD + o];
        sc += g_c2[(b * HH + h) * DD + o];
    }
    const float invS = 1.0f / SS, invD2 = 1.0f / 262144.0f;
    g_cb[b * DD + o] = invS * (sa + sc * invD2) + g_chat[o];
}

// ---------------- M2 split-K x4: z = b*4+kc ----------------
__global__ void __launch_bounds__(128, 2) k_Ms()
{
    extern __shared__ __half sm[];
    const int m0 = blockIdx.x * 128, n0 = blockIdx.y * 128, z = blockIdx.z;
    const int b = z >> 2, kc = z & 3;
    float acc[4][8][4];
    gemm_h<16>(g_gcat + (size_t)m0 * (HH*DD) + kc * 1024,
               g_ft + (size_t)b * DD * (HH*DD) + (size_t)n0 * (HH*DD) + kc * 1024,
               HH*DD, HH*DD, sm, acc);

    float* C = g_m2p + (size_t)z * DD * DD;
    const int lane = threadIdx.x & 31, warp = threadIdx.x >> 5;
    const int wm = (warp & 1) * 64, wn = (warp >> 1) * 64;
#pragma unroll
    for (int mi = 0; mi < 4; mi++)
#pragma unroll
        for (int ni = 0; ni < 8; ni++)
#pragma unroll
            for (int r = 0; r < 4; r++)
                C[(size_t)(m0 + EPI_ROW(wm, mi, r)) * DD + n0 + EPI_COL(wn, ni, r)] = acc[mi][ni][r];
}
__global__ void k_m2red()
{
    const int b = blockIdx.x, o = blockIdx.y, i = threadIdx.x;
    float a = 0.f;
#pragma unroll
    for (int kc = 0; kc < 4; kc++)
        a += g_m2p[((size_t)(b*4+kc) * DD + o) * DD + i];
    g_m2[((size_t)b * DD + o) * DD + i] = __float2half_rn(a);
}

// ---------------- out = invS*invD2*(X M2^T) + cb - invS*sum_h rm*a ----------------
__global__ void __launch_bounds__(128, 2) k_out2(float* __restrict__ out)
{
    extern __shared__ __half sm[];
    const int m0 = blockIdx.x * 128, n0 = blockIdx.y * 128;
    const int b = m0 >> 10;
    float acc[4][8][4];
    gemm_h<8>(g_xh + (size_t)m0 * DD,
              g_m2 + (size_t)b * DD * DD + (size_t)n0 * DD, DD, DD, sm, acc);

    __syncthreads();
    float* sA  = (float*)sm;
    float* srm = sA + 8 * 128;
    const int s0 = m0 & 1023;
    for (int i = threadIdx.x; i < 8 * 128; i += 128) {
        int h = i >> 7, l = i & 127;
        sA [i] = g_a [(b * HH + h) * DD + n0 + l];
        srm[i] = g_rm[(b * HH + h) * SS + s0 + l];
    }
    __syncthreads();

    const float invS = 1.0f / SS, invD2 = 1.0f / 262144.0f;
    const int lane = threadIdx.x & 31, warp = threadIdx.x >> 5;
    const int wm = (warp & 1) * 64, wn = (warp >> 1) * 64;
#pragma unroll
    for (int mi = 0; mi < 4; mi++)
#pragma unroll
        for (int ni = 0; ni < 8; ni++)
#pragma unroll
            for (int r = 0; r < 4; r++) {
                int rl = EPI_ROW(wm, mi, r);
                int cl = EPI_COL(wn, ni, r);
                float corr = 0.f;
#pragma unroll
                for (int h = 0; h < HH; h++) corr += srm[h * 128 + rl] * sA[h * 128 + cl];
                out[(size_t)(m0 + rl) * DD + n0 + cl] =
                    acc[mi][ni][r] * invS * invD2 + g_cb[b * DD + n0 + cl] - invS * corr;
            }
}

// ---------------- host launcher ----------------
extern "C" void kernel_launch(void* const* d_in, const int* in_sizes, int n_in,
                              void* d_out, int out_size)
{
    const float* X  = (const float*)d_in[0];
    const float* Wq = (const float*)d_in[1];
    const float* bq = (const float*)d_in[2];
    const float* Wk = (const float*)d_in[3];
    const float* bk = (const float*)d_in[4];
    const float* Wv = (const float*)d_in[5];
    const float* bv = (const float*)d_in[6];
    const float* Wo = (const float*)d_in[7];
    const float* bo = (const float*)d_in[8];
    float* out = (float*)d_out;
    (void)bk;

    const int SMEM = 3 * STG_H * 2;   // 98304 bytes
    cudaFuncSetAttribute(k_mgemm, cudaFuncAttributeMaxDynamicSharedMemorySize, SMEM);
    cudaFuncSetAttribute(k_G1s,   cudaFuncAttributeMaxDynamicSharedMemorySize, SMEM);
    cudaFuncSetAttribute(k_F,     cudaFuncAttributeMaxDynamicSharedMemorySize, SMEM);
    cudaFuncSetAttribute(k_Ms,    cudaFuncAttributeMaxDynamicSharedMemorySize, SMEM);
    cudaFuncSetAttribute(k_out2,  cudaFuncAttributeMaxDynamicSharedMemorySize, SMEM);

    k_cvt<<<2048, 256>>>(X, Wo);
    k_trw<<<dim3(16, 16, 24), dim3(32, 8)>>>(Wq, Wk, Wv);
    k_trx<<<dim3(16, 32, 8),  dim3(32, 8)>>>();
    k_colsum1<<<dim3(8, 8), 512>>>(X);
    k_csred<<<8, 512>>>();
    k_chat<<<512, 256>>>(Wo, bv, bo);
    k_r<<<dim3(8, 64), 256>>>(bq);
    k_mgemm<<<dim3(4, 4, 16), 128, SMEM>>>();
    k_vbar<<<64, 32>>>();
    k_w1<<<dim3(8, 64), 256>>>(Wv);
    k_w2<<<dim3(8, 64), 256>>>();
    k_rm<<<2048, 128>>>();
    k_G1s<<<dim3(4, 4, 16), 128, SMEM>>>();
    k_g1red<<<dim3(8, 512), 512>>>();
    k_vx<<<dim3(8, 64), 256>>>();
    k_F<<<dim3(4, 4, 64), 128, SMEM>>>();
    k_ac2<<<dim3(8, 64), 256>>>(Wo);
    k_cb<<<dim3(8, 4), 128>>>();
    k_Ms<<<dim3(4, 4, 32), 128, SMEM>>>();
    k_m2red<<<dim3(8, 512), 512>>>();
    k_out2<<<dim3(64, 4), 128, SMEM>>>(out);
}